// round 1
// baseline (speedup 1.0000x reference)
#include <cuda_runtime.h>
#include <cuda_bf16.h>

#define L     768
#define CIN   384
#define CO    32
#define NO    128
#define EPS   1e-5f

// Scratch (device globals - no allocation allowed)
__device__ float g_left [L * CO];
__device__ float g_right[L * CO];
__device__ float g_A    [L * NO];   // left  @ Wd   (768 x 128)
__device__ float g_Bm   [L * NO];   // right @ Wd   (768 x 128)

// ---------- f32x2 helpers (sm_100+ packed fp32 FMA) ----------
__device__ __forceinline__ unsigned long long pack2(float lo, float hi) {
    unsigned long long r;
    asm("mov.b64 %0, {%1, %2};" : "=l"(r) : "f"(lo), "f"(hi));
    return r;
}
__device__ __forceinline__ unsigned long long fma2(unsigned long long a,
                                                   unsigned long long b,
                                                   unsigned long long c) {
    unsigned long long d;
    asm("fma.rn.f32x2 %0, %1, %2, %3;" : "=l"(d) : "l"(a), "l"(b), "l"(c));
    return d;
}
__device__ __forceinline__ float2 unpack2(unsigned long long v) {
    float2 f;
    asm("mov.b64 {%0, %1}, %2;" : "=f"(f.x), "=f"(f.y) : "l"(v));
    return f;
}

// ============================================================================
// Kernel A: per-row LayerNorm -> left/right projections -> A, Bm rows
// One block per row j, 128 threads.
// ============================================================================
__global__ __launch_bounds__(128)
void prep_kernel(const float* __restrict__ act,  const float* __restrict__ mask,
                 const float* __restrict__ gamma, const float* __restrict__ beta,
                 const float* __restrict__ Wl,   const float* __restrict__ bl,
                 const float* __restrict__ Wr,   const float* __restrict__ br,
                 const float* __restrict__ Wo,   const float* __restrict__ bo)
{
    __shared__ float sx[CIN];
    __shared__ float sred[256];
    __shared__ float slr[2 * CO];

    const int j = blockIdx.x;
    const int t = threadIdx.x;
    const float* arow = act + j * CIN;

    float s = 0.f, s2 = 0.f;
    for (int c = t; c < CIN; c += 128) {
        float v = arow[c];
        sx[c] = v;
        s += v; s2 += v * v;
    }
    sred[t] = s; sred[128 + t] = s2;
    __syncthreads();
    for (int off = 64; off > 0; off >>= 1) {
        if (t < off) {
            sred[t]       += sred[t + off];
            sred[128 + t] += sred[128 + t + off];
        }
        __syncthreads();
    }
    const float mean = sred[0] * (1.f / CIN);
    const float var  = sred[128] * (1.f / CIN) - mean * mean;
    const float rstd = rsqrtf(var + EPS);

    for (int c = t; c < CIN; c += 128)
        sx[c] = (sx[c] - mean) * rstd * gamma[c] + beta[c];
    __syncthreads();

    // left / right projections: threads 0..31 -> left, 32..63 -> right
    if (t < 64) {
        const int c = t & 31;
        const float* W = (t < 32) ? Wl : Wr;
        float dot = 0.f;
        #pragma unroll 8
        for (int ci = 0; ci < CIN; ci++)
            dot += sx[ci] * W[ci * CO + c];
        const float bias = (t < 32) ? bl[c] : br[c];
        const float val  = mask[j] * (dot + bias);
        slr[t] = val;
        if (t < 32) g_left [j * CO + c] = val;
        else        g_right[j * CO + c] = val;
    }
    __syncthreads();

    // A[j,d] = sum_c left[j,c]*Wd[c,d];  Bm[j,d] = sum_c right[j,c]*Wd[c,d]
    {
        const int d = t;  // 0..127
        float a = 0.f, bm = 0.f;
        #pragma unroll
        for (int c = 0; c < CO; c++) {
            const float wd = Wo[(CO + c) * NO + d];
            a  += slr[c]      * wd;
            bm += slr[CO + c] * wd;
        }
        g_A [j * NO + d] = a;
        g_Bm[j * NO + d] = bm;
    }
}

// ============================================================================
// Kernel B: out[i,j,d] = sum_c left[j,c]*right[i,c]*Wp[c,d] + A[j,d] - Bm[i,d] + bo[d]
//
// Block: 256 threads = 2 groups of 128. Each group owns one i; thread owns one d.
// RW[c] = right[i,c]*Wp[c,d] duplicated into an f32x2 pair (loop-invariant over j).
// Shared holds a j-tile of left in (j-pair, c) interleaved layout so one LDS.128
// feeds two f32x2 FMAs (each FMA produces out for j0 and j1 simultaneously).
// ============================================================================
__global__ __launch_bounds__(256, 2)
void big_kernel(const float* __restrict__ Wo, const float* __restrict__ bo,
                float* __restrict__ out)
{
    // s_lp[(J*CO + c)*2 + p] = left[jt + 2J + p][c]
    __shared__ float s_lp[64 * CO];   // 8 KB

    const int t     = threadIdx.x;
    const int jt    = blockIdx.x * 64;
    const int group = t >> 7;         // 0 or 1
    const int d     = t & 127;
    const int i     = blockIdx.y * 2 + group;

    // Load left tile (coalesced read, interleaved write)
    const float* lp = g_left + jt * CO;
    for (int k = t; k < 64 * CO; k += 256) {
        const int jr = k >> 5;        // row in tile
        const int c  = k & 31;
        s_lp[(((jr >> 1) * CO + c) << 1) + (jr & 1)] = lp[k];
    }

    // Build duplicated RW pairs in registers
    unsigned long long RW[CO];
    {
        const float* rrow = g_right + i * CO;
        #pragma unroll
        for (int c = 0; c < CO; c++) {
            const float rw = rrow[c] * Wo[c * NO + d];
            RW[c] = pack2(rw, rw);
        }
    }
    const float base = bo[d] - g_Bm[i * NO + d];
    __syncthreads();

    float* orow = out + (size_t)i * L * NO + d;
    const float* Arow = g_A + d;

    #pragma unroll 1
    for (int J = 0; J < 32; J += 2) {
        const int j0 = jt + 2 * J;
        const float A00 = Arow[(size_t)(j0 + 0) * NO];
        const float A01 = Arow[(size_t)(j0 + 1) * NO];
        const float A10 = Arow[(size_t)(j0 + 2) * NO];
        const float A11 = Arow[(size_t)(j0 + 3) * NO];
        unsigned long long acc0 = pack2(base + A00, base + A01);
        unsigned long long acc1 = pack2(base + A10, base + A11);

        const float* p0 = &s_lp[(J * CO) << 1];
        const float* p1 = &s_lp[((J + 1) * CO) << 1];
        #pragma unroll
        for (int c = 0; c < CO; c += 2) {
            const ulonglong2 v0 = *(const ulonglong2*)&p0[c << 1];
            const ulonglong2 v1 = *(const ulonglong2*)&p1[c << 1];
            acc0 = fma2(v0.x, RW[c],     acc0);
            acc0 = fma2(v0.y, RW[c + 1], acc0);
            acc1 = fma2(v1.x, RW[c],     acc1);
            acc1 = fma2(v1.y, RW[c + 1], acc1);
        }
        const float2 r0 = unpack2(acc0);
        const float2 r1 = unpack2(acc1);
        orow[(size_t)(j0 + 0) * NO] = r0.x;
        orow[(size_t)(j0 + 1) * NO] = r0.y;
        orow[(size_t)(j0 + 2) * NO] = r1.x;
        orow[(size_t)(j0 + 3) * NO] = r1.y;
    }
}

// ============================================================================
extern "C" void kernel_launch(void* const* d_in, const int* in_sizes, int n_in,
                              void* d_out, int out_size)
{
    (void)in_sizes; (void)n_in; (void)out_size;
    const float* act   = (const float*)d_in[0];
    const float* mask  = (const float*)d_in[1];
    const float* gamma = (const float*)d_in[2];
    const float* beta  = (const float*)d_in[3];
    const float* Wl    = (const float*)d_in[4];
    const float* bl    = (const float*)d_in[5];
    const float* Wr    = (const float*)d_in[6];
    const float* br    = (const float*)d_in[7];
    const float* Wo    = (const float*)d_in[8];
    const float* bo    = (const float*)d_in[9];
    float* out = (float*)d_out;

    prep_kernel<<<L, 128>>>(act, mask, gamma, beta, Wl, bl, Wr, br, Wo, bo);

    dim3 grid(L / 64, L / 2);   // (12, 384)
    big_kernel<<<grid, 256>>>(Wo, bo, out);
}

// round 3
// speedup vs baseline: 1.1028x; 1.1028x over previous
#include <cuda_runtime.h>
#include <cuda_bf16.h>
#include <cstdint>

#define L     768
#define CIN   384
#define CO    32
#define NO    128
#define EPS   1e-5f

typedef unsigned long long u64;

// Scratch (device globals - no allocation allowed)
__device__ float g_left [L * CO];
__device__ float g_right[L * CO];
__device__ float g_Bm   [L * NO];   // right @ Wd   (768 x 128)

// ---------- f32x2 helpers (packed fp32 FMA, family-common on sm_10x) ----------
__device__ __forceinline__ u64 pack2(float lo, float hi) {
    u64 r;
    asm("mov.b64 %0, {%1, %2};" : "=l"(r) : "f"(lo), "f"(hi));
    return r;
}
__device__ __forceinline__ u64 fma2(u64 a, u64 b, u64 c) {
    u64 d;
    asm("fma.rn.f32x2 %0, %1, %2, %3;" : "=l"(d) : "l"(a), "l"(b), "l"(c));
    return d;
}
__device__ __forceinline__ float2 unpack2(u64 v) {
    float2 f;
    asm("mov.b64 {%0, %1}, %2;" : "=f"(f.x), "=f"(f.y) : "l"(v));
    return f;
}

// ============================================================================
// Kernel A: per-row LayerNorm -> left/right projections -> Bm rows
// One block per row j, 128 threads. Projections split: 128 threads = 2 (l/r)
// x 32 (c) x 2 (half of the 384-long dot), combined through shared memory.
// ============================================================================
__global__ __launch_bounds__(128)
void prep_kernel(const float* __restrict__ act,  const float* __restrict__ mask,
                 const float* __restrict__ gamma, const float* __restrict__ beta,
                 const float* __restrict__ Wl,   const float* __restrict__ bl,
                 const float* __restrict__ Wr,   const float* __restrict__ br,
                 const float* __restrict__ Wo)
{
    __shared__ float sx[CIN];
    __shared__ float sred[256];
    __shared__ float sdot[128];
    __shared__ float slr[2 * CO];

    const int j = blockIdx.x;
    const int t = threadIdx.x;
    const float* arow = act + j * CIN;

    float s = 0.f, s2 = 0.f;
    for (int c = t; c < CIN; c += 128) {
        float v = arow[c];
        sx[c] = v;
        s += v; s2 += v * v;
    }
    sred[t] = s; sred[128 + t] = s2;
    __syncthreads();
    for (int off = 64; off > 0; off >>= 1) {
        if (t < off) {
            sred[t]       += sred[t + off];
            sred[128 + t] += sred[128 + t + off];
        }
        __syncthreads();
    }
    const float mean = sred[0] * (1.f / CIN);
    const float var  = sred[128] * (1.f / CIN) - mean * mean;
    const float rstd = rsqrtf(var + EPS);

    for (int c = t; c < CIN; c += 128)
        sx[c] = (sx[c] - mean) * rstd * gamma[c] + beta[c];
    __syncthreads();

    // Projections: lr = t>>6, half = (t>>5)&1, c = t&31
    {
        const int lr   = t >> 6;
        const int half = (t >> 5) & 1;
        const int c    = t & 31;
        const float* W = lr ? Wr : Wl;
        const int ci0  = half * (CIN / 2);
        float dot = 0.f;
        #pragma unroll 8
        for (int ci = ci0; ci < ci0 + CIN / 2; ci++)
            dot += sx[ci] * W[ci * CO + c];
        sdot[t] = dot;
    }
    __syncthreads();
    if ((t & 32) == 0) {   // half == 0 threads combine
        const int lr = t >> 6;
        const int c  = t & 31;
        const float bias = lr ? br[c] : bl[c];
        const float val  = mask[j] * (sdot[t] + sdot[t | 32] + bias);
        slr[lr * CO + c] = val;
        if (lr == 0) g_left [j * CO + c] = val;
        else         g_right[j * CO + c] = val;
    }
    __syncthreads();

    // Bm[j,d] = sum_c right[j,c]*Wd[c,d]
    {
        const int d = t;  // 0..127
        float bm = 0.f;
        #pragma unroll
        for (int c = 0; c < CO; c++)
            bm += slr[CO + c] * Wo[(CO + c) * NO + d];
        g_Bm[j * NO + d] = bm;
    }
}

// ============================================================================
// Kernel B: out[i, jt+j, d] = sum_c left[jt+j, c] * B2[c, d] + (bo[d]-Bm[i,d])
//   B2[c,d] = right[i,c]*Wp[c,d] + Wd[c,d]   (diff-term folded algebraically)
//
// Block = (one i, 128-j tile, all 128 d). 256 threads, 8j x 8d per thread.
// Shared: left^T[c][j] (A-frags are natural j-pairs -> direct f32x2 operands,
// 16-way warp broadcast reads) and B2[c][d] (d-contiguous, dup'd into pairs
// once per k, reused across 4 j-pairs). 32 fma2 per 4 LDS.128 per thread-k.
// ============================================================================
__global__ __launch_bounds__(256, 2)
void big_kernel(const float* __restrict__ Wo, const float* __restrict__ bo,
                float* __restrict__ out)
{
    __shared__ float s_lt[CO * 128];   // [c][j]  16 KB
    __shared__ float s_b [CO * 128];   // [c][d]  16 KB
    __shared__ float s_base[128];

    const int t  = threadIdx.x;
    const int jt = blockIdx.x * 128;
    const int i  = blockIdx.y;

    if (t < 128) {
        // Transpose left rows jt..jt+127 into s_lt[c][j]
        const float4* lp = (const float4*)(g_left + (jt + t) * CO);
        #pragma unroll
        for (int q = 0; q < 8; q++) {
            float4 v = lp[q];
            s_lt[(q * 4 + 0) * 128 + t] = v.x;
            s_lt[(q * 4 + 1) * 128 + t] = v.y;
            s_lt[(q * 4 + 2) * 128 + t] = v.z;
            s_lt[(q * 4 + 3) * 128 + t] = v.w;
        }
    } else {
        const int d = t - 128;  // 0..127 : one d-column of B2
        const float* rrow = g_right + i * CO;
        #pragma unroll 8
        for (int c = 0; c < CO; c++)
            s_b[c * 128 + d] = __ldg(&rrow[c]) * Wo[c * NO + d]
                             + Wo[(CO + c) * NO + d];
        s_base[d] = bo[d] - g_Bm[i * NO + d];
    }
    __syncthreads();

    const int jg = t >> 4;      // 0..15
    const int dg = t & 15;      // 0..15
    const int j0 = jg * 8;
    const int d0 = dg * 8;

    u64 acc[4][8];
    {
        u64 binit[8];
        #pragma unroll
        for (int dd = 0; dd < 8; dd++) {
            float b = s_base[d0 + dd];
            binit[dd] = pack2(b, b);
        }
        #pragma unroll
        for (int jp = 0; jp < 4; jp++)
            #pragma unroll
            for (int dd = 0; dd < 8; dd++)
                acc[jp][dd] = binit[dd];
    }

    #pragma unroll 8
    for (int k = 0; k < CO; k++) {
        const ulonglong2 a01 = *(const ulonglong2*)&s_lt[k * 128 + j0];
        const ulonglong2 a23 = *(const ulonglong2*)&s_lt[k * 128 + j0 + 4];
        const float4 bA = *(const float4*)&s_b[k * 128 + d0];
        const float4 bB = *(const float4*)&s_b[k * 128 + d0 + 4];
        u64 bb[8];
        bb[0] = pack2(bA.x, bA.x); bb[1] = pack2(bA.y, bA.y);
        bb[2] = pack2(bA.z, bA.z); bb[3] = pack2(bA.w, bA.w);
        bb[4] = pack2(bB.x, bB.x); bb[5] = pack2(bB.y, bB.y);
        bb[6] = pack2(bB.z, bB.z); bb[7] = pack2(bB.w, bB.w);
        #pragma unroll
        for (int dd = 0; dd < 8; dd++) {
            acc[0][dd] = fma2(a01.x, bb[dd], acc[0][dd]);
            acc[1][dd] = fma2(a01.y, bb[dd], acc[1][dd]);
            acc[2][dd] = fma2(a23.x, bb[dd], acc[2][dd]);
            acc[3][dd] = fma2(a23.y, bb[dd], acc[3][dd]);
        }
    }

    // Epilogue: 8 rows x 8 d per thread, 2 STG.128 per row
    float* op = out + ((size_t)i * L + jt + j0) * NO + d0;
    #pragma unroll
    for (int jp = 0; jp < 4; jp++) {
        float ra[8], rb[8];
        #pragma unroll
        for (int dd = 0; dd < 8; dd++) {
            float2 v = unpack2(acc[jp][dd]);
            ra[dd] = v.x; rb[dd] = v.y;
        }
        float4* r0p = (float4*)(op + (size_t)(2 * jp) * NO);
        float4* r1p = (float4*)(op + (size_t)(2 * jp + 1) * NO);
        r0p[0] = make_float4(ra[0], ra[1], ra[2], ra[3]);
        r0p[1] = make_float4(ra[4], ra[5], ra[6], ra[7]);
        r1p[0] = make_float4(rb[0], rb[1], rb[2], rb[3]);
        r1p[1] = make_float4(rb[4], rb[5], rb[6], rb[7]);
    }
}

// ============================================================================
extern "C" void kernel_launch(void* const* d_in, const int* in_sizes, int n_in,
                              void* d_out, int out_size)
{
    (void)in_sizes; (void)n_in; (void)out_size;
    const float* act   = (const float*)d_in[0];
    const float* mask  = (const float*)d_in[1];
    const float* gamma = (const float*)d_in[2];
    const float* beta  = (const float*)d_in[3];
    const float* Wl    = (const float*)d_in[4];
    const float* bl    = (const float*)d_in[5];
    const float* Wr    = (const float*)d_in[6];
    const float* br    = (const float*)d_in[7];
    const float* Wo    = (const float*)d_in[8];
    const float* bo    = (const float*)d_in[9];
    float* out = (float*)d_out;

    prep_kernel<<<L, 128>>>(act, mask, gamma, beta, Wl, bl, Wr, br, Wo);

    dim3 grid(L / 128, L);   // (6, 768)
    big_kernel<<<grid, 256>>>(Wo, bo, out);
}

// round 4
// speedup vs baseline: 1.6164x; 1.4658x over previous
#include <cuda_runtime.h>
#include <cuda_bf16.h>
#include <cstdint>

#define L     768
#define CIN   384
#define CO    32
#define NO    128
#define EPS   1e-5f

// ---------------- device scratch (no allocations allowed) ----------------
__device__ float          g_right[L * CO];
__device__ float          g_Bm   [L * NO];          // right @ Wd (768x128)
__device__ __nv_bfloat16  g_lh   [L * CO];          // left hi
__device__ __nv_bfloat16  g_ll   [L * CO];          // left lo
__device__ __nv_bfloat16  g_B2h  [(size_t)L * CO * NO];  // per-i B2 hi  [i][c][d]
__device__ __nv_bfloat16  g_B2l  [(size_t)L * CO * NO];  // per-i B2 lo

// ---------------- PTX helpers (family-common, sm_80+) ----------------
__device__ __forceinline__ uint32_t smem_u32(const void* p) {
    uint32_t a;
    asm("{ .reg .u64 t; cvta.to.shared.u64 t, %1; cvt.u32.u64 %0, t; }"
        : "=r"(a) : "l"(p));
    return a;
}
__device__ __forceinline__ void ldsm_x4(uint32_t* r, uint32_t addr) {
    asm volatile("ldmatrix.sync.aligned.m8n8.x4.shared.b16 {%0,%1,%2,%3}, [%4];"
                 : "=r"(r[0]), "=r"(r[1]), "=r"(r[2]), "=r"(r[3]) : "r"(addr));
}
__device__ __forceinline__ void ldsm_x4t(uint32_t* r, uint32_t addr) {
    asm volatile("ldmatrix.sync.aligned.m8n8.x4.trans.shared.b16 {%0,%1,%2,%3}, [%4];"
                 : "=r"(r[0]), "=r"(r[1]), "=r"(r[2]), "=r"(r[3]) : "r"(addr));
}
__device__ __forceinline__ void mma16816(float* d, const uint32_t* a, const uint32_t* b) {
    asm volatile(
        "mma.sync.aligned.m16n8k16.row.col.f32.bf16.bf16.f32 "
        "{%0,%1,%2,%3}, {%4,%5,%6,%7}, {%8,%9}, {%0,%1,%2,%3};"
        : "+f"(d[0]), "+f"(d[1]), "+f"(d[2]), "+f"(d[3])
        : "r"(a[0]), "r"(a[1]), "r"(a[2]), "r"(a[3]), "r"(b[0]), "r"(b[1]));
}

// ============================================================================
// Kernel A: per-row LayerNorm -> left/right projections -> Bm + bf16 left split
// ============================================================================
__global__ __launch_bounds__(128)
void prep_kernel(const float* __restrict__ act,  const float* __restrict__ mask,
                 const float* __restrict__ gamma, const float* __restrict__ beta,
                 const float* __restrict__ Wl,   const float* __restrict__ bl,
                 const float* __restrict__ Wr,   const float* __restrict__ br,
                 const float* __restrict__ Wo)
{
    __shared__ float sx[CIN];
    __shared__ float sred[256];
    __shared__ float sdot[128];
    __shared__ float slr[2 * CO];

    const int j = blockIdx.x;
    const int t = threadIdx.x;
    const float* arow = act + j * CIN;

    float s = 0.f, s2 = 0.f;
    for (int c = t; c < CIN; c += 128) {
        float v = arow[c];
        sx[c] = v;
        s += v; s2 += v * v;
    }
    sred[t] = s; sred[128 + t] = s2;
    __syncthreads();
    for (int off = 64; off > 0; off >>= 1) {
        if (t < off) {
            sred[t]       += sred[t + off];
            sred[128 + t] += sred[128 + t + off];
        }
        __syncthreads();
    }
    const float mean = sred[0] * (1.f / CIN);
    const float var  = sred[128] * (1.f / CIN) - mean * mean;
    const float rstd = rsqrtf(var + EPS);

    for (int c = t; c < CIN; c += 128)
        sx[c] = (sx[c] - mean) * rstd * gamma[c] + beta[c];
    __syncthreads();

    // Projections: lr = t>>6, half = (t>>5)&1, c = t&31
    {
        const int lr   = t >> 6;
        const int half = (t >> 5) & 1;
        const int c    = t & 31;
        const float* W = lr ? Wr : Wl;
        const int ci0  = half * (CIN / 2);
        float dot = 0.f;
        #pragma unroll 8
        for (int ci = ci0; ci < ci0 + CIN / 2; ci++)
            dot += sx[ci] * W[ci * CO + c];
        sdot[t] = dot;
    }
    __syncthreads();
    if ((t & 32) == 0) {
        const int lr = t >> 6;
        const int c  = t & 31;
        const float bias = lr ? br[c] : bl[c];
        const float val  = mask[j] * (sdot[t] + sdot[t | 32] + bias);
        slr[lr * CO + c] = val;
        if (lr == 0) {
            __nv_bfloat16 h = __float2bfloat16_rn(val);
            g_lh[j * CO + c] = h;
            g_ll[j * CO + c] = __float2bfloat16_rn(val - __bfloat162float(h));
        } else {
            g_right[j * CO + c] = val;
        }
    }
    __syncthreads();

    // Bm[j,d] = sum_c right[j,c]*Wd[c,d]
    {
        const int d = t;  // 0..127
        float bm = 0.f;
        #pragma unroll
        for (int c = 0; c < CO; c++)
            bm += slr[CO + c] * Wo[(CO + c) * NO + d];
        g_Bm[j * NO + d] = bm;
    }
}

// ============================================================================
// Kernel A2: per-i B2 = right[i,c]*Wp[c,d] + Wd[c,d], bf16 hi/lo split
// ============================================================================
__global__ __launch_bounds__(128)
void prep2_kernel(const float* __restrict__ Wo)
{
    __shared__ float sR[CO];
    const int i = blockIdx.x;
    const int d = threadIdx.x;  // 0..127
    if (d < CO) sR[d] = g_right[i * CO + d];
    __syncthreads();

    __nv_bfloat16* bh = g_B2h + (size_t)i * CO * NO + d;
    __nv_bfloat16* bl = g_B2l + (size_t)i * CO * NO + d;
    #pragma unroll 8
    for (int c = 0; c < CO; c++) {
        float v = sR[c] * Wo[c * NO + d] + Wo[(CO + c) * NO + d];
        __nv_bfloat16 h = __float2bfloat16_rn(v);
        bh[c * NO] = h;
        bl[c * NO] = __float2bfloat16_rn(v - __bfloat162float(h));
    }
}

// ============================================================================
// Kernel B: per (i, 128-j tile): D = A(128xK96) @ B(K96x128) via mma.sync bf16
//   logical K=96 = [lh*bh | lh*bl | ll*bh]; physical smem K=64 (lh/ll, bh/bl)
//   acc initialized with (bo[d] - Bm[i,d]) -> epilogue is pure stores.
// 8 warps: 4 m-strips(32) x 2 n-strips(64); warp = 2 m-tiles x 8 n-tiles.
// ============================================================================
#define SA_STRIDE 72     // 144B rows: mult of 16, 36 words %32 = 4 (conflict-free)
#define SB_STRIDE 136    // 272B rows: mult of 16, 68 words %32 = 4 (conflict-free)

__global__ __launch_bounds__(256, 2)
void big_kernel(const float* __restrict__ bo, float* __restrict__ out)
{
    __shared__ __nv_bfloat16 sA[128 * SA_STRIDE];  // rows j, k0-31=lh, k32-63=ll
    __shared__ __nv_bfloat16 sB[64 * SB_STRIDE];   // rows k (0-31=bh, 32-63=bl), cols d
    __shared__ float sBase[NO];

    const int t  = threadIdx.x;
    const int i  = blockIdx.x;
    const int jt = blockIdx.y * 128;

    // ---- stage sA: 128 rows x 2 sections x 4 uint4-chunks ----
    for (int idx = t; idx < 1024; idx += 256) {
        const int j  = idx >> 3;
        const int s  = (idx >> 2) & 1;
        const int ch = idx & 3;
        const uint4 v = s ? ((const uint4*)(g_ll + (jt + j) * CO))[ch]
                          : ((const uint4*)(g_lh + (jt + j) * CO))[ch];
        *(uint4*)((char*)sA + (j * SA_STRIDE + s * 32 + ch * 8) * 2) = v;
    }
    // ---- stage sB: 64 rows x 16 uint4-chunks ----
    {
        const uint4* srcH = (const uint4*)(g_B2h + (size_t)i * CO * NO);
        const uint4* srcL = (const uint4*)(g_B2l + (size_t)i * CO * NO);
        for (int idx = t; idx < 1024; idx += 256) {
            const int r  = idx >> 4;
            const int ch = idx & 15;
            const uint4 v = (r < 32) ? srcH[r * 16 + ch] : srcL[(r - 32) * 16 + ch];
            *(uint4*)((char*)sB + (r * SB_STRIDE + ch * 8) * 2) = v;
        }
    }
    if (t < 128) sBase[t] = bo[t] - g_Bm[i * NO + t];
    __syncthreads();

    const int lane = t & 31;
    const int wid  = t >> 5;
    const int mOff = (wid & 3) * 32;
    const int nOff = (wid >> 2) * 64;

    const uint32_t saBase = smem_u32(sA);
    const uint32_t sbBase = smem_u32(sB);
    // A: row = mOff + (lane&15) [+16 per m-tile], col = ka + (lane>>4)*8
    const uint32_t aAddr0 = saBase + ((mOff + (lane & 15)) * SA_STRIDE + (lane >> 4) * 8) * 2;
    // B: row k = kb + (lane&15), col = nOff + (lane>>4)*8 [+16 per q]
    const uint32_t bAddr0 = sbBase + ((lane & 15) * SB_STRIDE + nOff + (lane >> 4) * 8) * 2;

    float acc[2][8][4];
    #pragma unroll
    for (int nt = 0; nt < 8; nt++) {
        const float2 bb = *(const float2*)&sBase[nOff + nt * 8 + (lane & 3) * 2];
        #pragma unroll
        for (int mt = 0; mt < 2; mt++) {
            acc[mt][nt][0] = bb.x; acc[mt][nt][1] = bb.y;
            acc[mt][nt][2] = bb.x; acc[mt][nt][3] = bb.y;
        }
    }

    // logical k-steps: (lh,bh)x2, (lh,bl)x2, (ll,bh)x2
    const int aK[6] = {0, 16, 0, 16, 32, 48};
    const int bK[6] = {0, 16, 32, 48, 0, 16};

    #pragma unroll
    for (int ks = 0; ks < 6; ks++) {
        uint32_t af[2][4], bf[4][4];
        ldsm_x4(af[0], aAddr0 + (uint32_t)(aK[ks] * 2));
        ldsm_x4(af[1], aAddr0 + (uint32_t)((16 * SA_STRIDE + aK[ks]) * 2));
        #pragma unroll
        for (int q = 0; q < 4; q++)
            ldsm_x4t(bf[q], bAddr0 + (uint32_t)((bK[ks] * SB_STRIDE + q * 16) * 2));
        #pragma unroll
        for (int mt = 0; mt < 2; mt++)
            #pragma unroll
            for (int nt = 0; nt < 8; nt++)
                mma16816(acc[mt][nt], af[mt], &bf[nt >> 1][(nt & 1) * 2]);
    }

    // ---- epilogue: pure STG.64 (base already folded into acc) ----
    const int dBase = nOff + (lane & 3) * 2;
    float* outI = out + ((size_t)i * L + jt) * NO;
    #pragma unroll
    for (int mt = 0; mt < 2; mt++) {
        const int r0 = mOff + mt * 16 + (lane >> 2);
        float* p0 = outI + (size_t)r0 * NO;
        float* p1 = p0 + 8 * NO;
        #pragma unroll
        for (int nt = 0; nt < 8; nt++) {
            const int d = dBase + nt * 8;
            *(float2*)(p0 + d) = make_float2(acc[mt][nt][0], acc[mt][nt][1]);
            *(float2*)(p1 + d) = make_float2(acc[mt][nt][2], acc[mt][nt][3]);
        }
    }
}

// ============================================================================
extern "C" void kernel_launch(void* const* d_in, const int* in_sizes, int n_in,
                              void* d_out, int out_size)
{
    (void)in_sizes; (void)n_in; (void)out_size;
    const float* act   = (const float*)d_in[0];
    const float* mask  = (const float*)d_in[1];
    const float* gamma = (const float*)d_in[2];
    const float* beta  = (const float*)d_in[3];
    const float* Wl    = (const float*)d_in[4];
    const float* bl    = (const float*)d_in[5];
    const float* Wr    = (const float*)d_in[6];
    const float* br    = (const float*)d_in[7];
    const float* Wo    = (const float*)d_in[8];
    const float* bo    = (const float*)d_in[9];
    float* out = (float*)d_out;

    prep_kernel<<<L, 128>>>(act, mask, gamma, beta, Wl, bl, Wr, br, Wo);
    prep2_kernel<<<L, 128>>>(Wo);

    dim3 grid(L, L / 128);   // (768 i, 6 j-tiles)
    big_kernel<<<grid, 256>>>(bo, out);
}